// round 9
// baseline (speedup 1.0000x reference)
#include <cuda_runtime.h>

// ---------------------------------------------------------------------------
// EncodeProcessDecode GNN, fp32 packed f32x2 FMA, L1-wavefront-optimized tiling.
//  - Config A (128-col layers): warp owns 32 cols; lane = (col-group, row-group)
//      c0 = 32*w + (l&7)*4 ; r0 = (l>>3)*8 ; acc[4 row-pairs][4 cols]
//      per k: 1 bcast LDG.128 (1 wf) + 2 bcast LDS.128 (2 wf) + 16 fma2
//  - Config B (64-col layers): c0 = 16*w + (l&3)*4 ; r0 = (l>>2)*4 ; acc[2][4]
//      per k: 1 LDG (1 wf) + 1 LDS.128 (1 wf) + 8 fma2
// ---------------------------------------------------------------------------

#define SROW 36            // shared row stride (floats), mult of 4 -> 16B-aligned rows
#define MAXN 50048
#define MAXE 800032

typedef unsigned long long ull;

__device__ float g_node[(size_t)MAXN * 128];
__device__ float g_edge_tail[(size_t)MAXE * 64];
__device__ float g_Pd[(size_t)MAXN * 128];     // node_tail @ W0[64:128] + b0
__device__ float g_Ps[(size_t)MAXN * 128];     // node_tail @ W0[128:192]
__device__ float g_agg[(size_t)MAXN * 64];
__device__ float g_counts[MAXN];

// ---- packed f32x2 helpers --------------------------------------------------
__device__ __forceinline__ ull pk2(float a, float b) {
    ull r;
    asm("mov.b64 %0, {%1, %2};" : "=l"(r) : "f"(a), "f"(b));
    return r;
}
__device__ __forceinline__ void upk2(ull v, float &a, float &b) {
    asm("mov.b64 {%0, %1}, %2;" : "=f"(a), "=f"(b) : "l"(v));
}
__device__ __forceinline__ void fma2(ull &d, ull a, ull b) {
    asm("fma.rn.f32x2 %0, %1, %2, %3;" : "=l"(d) : "l"(a), "l"(b), "l"(d));
}
__device__ __forceinline__ ull add2(ull a, ull b) {
    ull r;
    asm("add.rn.f32x2 %0, %1, %2;" : "=l"(r) : "l"(a), "l"(b));
    return r;
}

// ---- GEMM mainloops ---------------------------------------------------------
// Config A: 4 row-pairs x 4 cols per thread.
__device__ __forceinline__ void gemmA(ull (&acc)[4][4],
                                      const float* __restrict__ W, int ld, int K,
                                      const float* sInT, int c0, int r0) {
#pragma unroll 4
    for (int k = 0; k < K; k++) {
        float4 w = __ldg(reinterpret_cast<const float4*>(W + (size_t)k * ld + c0));
        ull w0 = pk2(w.x, w.x), w1 = pk2(w.y, w.y);
        ull w2 = pk2(w.z, w.z), w3 = pk2(w.w, w.w);
        const float* row = sInT + k * SROW + r0;
        ulonglong2 xa = *reinterpret_cast<const ulonglong2*>(row);       // rows r0..r0+3
        ulonglong2 xb = *reinterpret_cast<const ulonglong2*>(row + 4);   // rows r0+4..r0+7
        fma2(acc[0][0], xa.x, w0); fma2(acc[0][1], xa.x, w1);
        fma2(acc[0][2], xa.x, w2); fma2(acc[0][3], xa.x, w3);
        fma2(acc[1][0], xa.y, w0); fma2(acc[1][1], xa.y, w1);
        fma2(acc[1][2], xa.y, w2); fma2(acc[1][3], xa.y, w3);
        fma2(acc[2][0], xb.x, w0); fma2(acc[2][1], xb.x, w1);
        fma2(acc[2][2], xb.x, w2); fma2(acc[2][3], xb.x, w3);
        fma2(acc[3][0], xb.y, w0); fma2(acc[3][1], xb.y, w1);
        fma2(acc[3][2], xb.y, w2); fma2(acc[3][3], xb.y, w3);
    }
}

// Config B: 2 row-pairs x 4 cols per thread.
__device__ __forceinline__ void gemmB(ull (&acc)[2][4],
                                      const float* __restrict__ W, int ld, int K,
                                      const float* sInT, int c0, int r0) {
#pragma unroll 4
    for (int k = 0; k < K; k++) {
        float4 w = __ldg(reinterpret_cast<const float4*>(W + (size_t)k * ld + c0));
        ull w0 = pk2(w.x, w.x), w1 = pk2(w.y, w.y);
        ull w2 = pk2(w.z, w.z), w3 = pk2(w.w, w.w);
        ulonglong2 xa =
            *reinterpret_cast<const ulonglong2*>(sInT + k * SROW + r0);  // rows r0..r0+3
        fma2(acc[0][0], xa.x, w0); fma2(acc[0][1], xa.x, w1);
        fma2(acc[0][2], xa.x, w2); fma2(acc[0][3], xa.x, w3);
        fma2(acc[1][0], xa.y, w0); fma2(acc[1][1], xa.y, w1);
        fma2(acc[1][2], xa.y, w2); fma2(acc[1][3], xa.y, w3);
    }
}

template <int NP>
__device__ __forceinline__ void init_bias(ull (&acc)[NP][4],
                                          const float* __restrict__ b, int c0) {
#pragma unroll
    for (int c = 0; c < 4; c++) {
        float bv = b[c0 + c];
        ull bb = pk2(bv, bv);
#pragma unroll
        for (int p = 0; p < NP; p++) acc[p][c] = bb;
    }
}

__device__ __forceinline__ void relu_store_hT(ull (&acc)[4][4],
                                              float* sHT, int c0, int r0) {
#pragma unroll
    for (int p = 0; p < 4; p++)
#pragma unroll
        for (int c = 0; c < 4; c++) {
            float a, b;
            upk2(acc[p][c], a, b);
            a = fmaxf(a, 0.f);
            b = fmaxf(b, 0.f);
            *reinterpret_cast<float2*>(&sHT[(c0 + c) * SROW + r0 + 2 * p]) =
                make_float2(a, b);
        }
}

// ---------------------------------------------------------------------------
// utility kernels
// ---------------------------------------------------------------------------
__global__ void k_zero_counts(int n) {
    int i = blockIdx.x * 256 + threadIdx.x;
    if (i < n) g_counts[i] = 0.f;
}
__global__ void k_zero_agg(int n) {
    int i = blockIdx.x * 256 + threadIdx.x;
    if (i < n) g_agg[i] = 0.f;
}
__global__ void k_counts(const int* __restrict__ ei, int E) {
    int e = blockIdx.x * 256 + threadIdx.x;
    if (e < E) atomicAdd(&g_counts[ei[E + e]], 1.0f);  // dst = ei[1][e]
}

// ---------------------------------------------------------------------------
// encode node: x = [nf[:, :31], emb[ptype]] (K=47) -> 128 relu -> 128
// ---------------------------------------------------------------------------
__global__ void __launch_bounds__(128)
k_encode_node(const float* __restrict__ nf, const float* __restrict__ emb,
              const float* __restrict__ W0, const float* __restrict__ b0,
              const float* __restrict__ W1, const float* __restrict__ b1, int N) {
    __shared__ float sInT[47 * SROW];
    __shared__ float sHT[128 * SROW];
    __shared__ int sPT[32];
    int t = threadIdx.x;
    int base = blockIdx.x * 32;

    if (t < 32) {
        int n = min(base + t, N - 1);
        sPT[t] = (int)(nf[n * 32 + 31] + 0.5f);
    }
    __syncthreads();
    for (int i = t; i < 32 * 47; i += 128) {
        int r = i / 47, k = i - r * 47;
        int n = min(base + r, N - 1);
        float v = (k < 31) ? nf[n * 32 + k] : emb[sPT[r] * 16 + (k - 31)];
        sInT[k * SROW + r] = v;
    }
    __syncthreads();

    int w = t >> 5, l = t & 31;
    int c0 = 32 * w + (l & 7) * 4, r0 = (l >> 3) * 8;
    ull acc[4][4];
    init_bias<4>(acc, b0, c0);
    gemmA(acc, W0, 128, 47, sInT, c0, r0);
    relu_store_hT(acc, sHT, c0, r0);
    __syncthreads();

    ull acc2[4][4];
    init_bias<4>(acc2, b1, c0);
    gemmA(acc2, W1, 128, 128, sHT, c0, r0);
#pragma unroll
    for (int p = 0; p < 4; p++)
#pragma unroll
        for (int c = 0; c < 4; c++) {
            float a, b;
            upk2(acc2[p][c], a, b);
            int rA = base + r0 + 2 * p;
            if (rA < N)     g_node[(size_t)rA * 128 + c0 + c] = a;
            if (rA + 1 < N) g_node[(size_t)(rA + 1) * 128 + c0 + c] = b;
        }
}

// ---------------------------------------------------------------------------
// encode edge: K=3 -> 128 relu -> cols 64..127 only (tail) -> g_edge_tail
// ---------------------------------------------------------------------------
__global__ void __launch_bounds__(128)
k_encode_edge(const float* __restrict__ ef,
              const float* __restrict__ W0, const float* __restrict__ b0,
              const float* __restrict__ W1, const float* __restrict__ b1, int E) {
    __shared__ float sInT[3 * SROW];
    __shared__ float sHT[128 * SROW];
    int t = threadIdx.x;
    int base = blockIdx.x * 32;

    for (int i = t; i < 32 * 3; i += 128) {
        int r = i / 3, k = i - r * 3;
        int e = min(base + r, E - 1);
        sInT[k * SROW + r] = ef[e * 3 + k];
    }
    __syncthreads();

    int w = t >> 5, l = t & 31;
    int c0 = 32 * w + (l & 7) * 4, r0 = (l >> 3) * 8;
    ull acc[4][4];
    init_bias<4>(acc, b0, c0);
    gemmA(acc, W0, 128, 3, sInT, c0, r0);
    relu_store_hT(acc, sHT, c0, r0);
    __syncthreads();

    // layer 2: only output columns 64..127 (edge tail), config B
    int c0b = 16 * w + (l & 3) * 4, r0b = (l >> 2) * 4;
    ull acc2[2][4];
    init_bias<2>(acc2, b1 + 64, c0b);
    gemmB(acc2, W1 + 64, 128, 128, sHT, c0b, r0b);
#pragma unroll
    for (int p = 0; p < 2; p++)
#pragma unroll
        for (int c = 0; c < 4; c++) {
            float a, b;
            upk2(acc2[p][c], a, b);
            int eA = base + r0b + 2 * p;
            if (eA < E)     g_edge_tail[(size_t)eA * 64 + c0b + c] = a;
            if (eA + 1 < E) g_edge_tail[(size_t)(eA + 1) * 64 + c0b + c] = b;
        }
}

// ---------------------------------------------------------------------------
// node projections for the factorized edge layer-1:
//   Pd = node_tail @ W0[64:128]  + b0
//   Ps = node_tail @ W0[128:192]
// ---------------------------------------------------------------------------
__global__ void __launch_bounds__(128)
k_node_proj(const float* __restrict__ W0, const float* __restrict__ b0, int N) {
    __shared__ float sInT[64 * SROW];
    int t = threadIdx.x;
    int base = blockIdx.x * 32;

    for (int i = t; i < 32 * 64; i += 128) {
        int r = i >> 6, k = i & 63;
        int n = min(base + r, N - 1);
        sInT[k * SROW + r] = g_node[(size_t)n * 128 + 64 + k];
    }
    __syncthreads();

    int w = t >> 5, l = t & 31;
    int c0 = 32 * w + (l & 7) * 4, r0 = (l >> 3) * 8;

    ull acc[4][4];
    init_bias<4>(acc, b0, c0);
    gemmA(acc, W0 + 64 * 128, 128, 64, sInT, c0, r0);
#pragma unroll
    for (int p = 0; p < 4; p++)
#pragma unroll
        for (int c = 0; c < 4; c++) {
            float a, b;
            upk2(acc[p][c], a, b);
            int rA = base + r0 + 2 * p;
            if (rA < N)     g_Pd[(size_t)rA * 128 + c0 + c] = a;
            if (rA + 1 < N) g_Pd[(size_t)(rA + 1) * 128 + c0 + c] = b;
        }

    ull acc2[4][4];
#pragma unroll
    for (int c = 0; c < 4; c++)
#pragma unroll
        for (int p = 0; p < 4; p++) acc2[p][c] = 0ull;
    gemmA(acc2, W0 + 128 * 128, 128, 64, sInT, c0, r0);
#pragma unroll
    for (int p = 0; p < 4; p++)
#pragma unroll
        for (int c = 0; c < 4; c++) {
            float a, b;
            upk2(acc2[p][c], a, b);
            int rA = base + r0 + 2 * p;
            if (rA < N)     g_Ps[(size_t)rA * 128 + c0 + c] = a;
            if (rA + 1 < N) g_Ps[(size_t)(rA + 1) * 128 + c0 + c] = b;
        }
}

// ---------------------------------------------------------------------------
// core edge step (fused):
//   h    = relu(tail @ W0[0:64] + Pd[dst] + Ps[src])
//   eout = h @ W1 + b1 ; tail += eout ; store ; atomicAdd into g_agg[dst]
// ---------------------------------------------------------------------------
__global__ void __launch_bounds__(128)
k_edge_core(const int* __restrict__ ei, const float* __restrict__ W0,
            const float* __restrict__ W1, const float* __restrict__ b1, int E) {
    __shared__ float sInT[64 * SROW];
    __shared__ float sHT[128 * SROW];
    __shared__ int sDst[32], sSrc[32];
    int t = threadIdx.x;
    int base = blockIdx.x * 32;

    if (t < 32) {
        int e = min(base + t, E - 1);
        sSrc[t] = ei[e];
        sDst[t] = ei[E + e];
    }
    for (int i = t; i < 32 * 64; i += 128) {
        int r = i >> 6, k = i & 63;
        int e = min(base + r, E - 1);
        sInT[k * SROW + r] = g_edge_tail[(size_t)e * 64 + k];
    }
    __syncthreads();

    int w = t >> 5, l = t & 31;
    int c0 = 32 * w + (l & 7) * 4, r0 = (l >> 3) * 8;
    ull acc[4][4];
#pragma unroll
    for (int p = 0; p < 4; p++) {
        int rA = r0 + 2 * p;
        float4 pA = *reinterpret_cast<const float4*>(&g_Pd[(size_t)sDst[rA] * 128 + c0]);
        float4 qA = *reinterpret_cast<const float4*>(&g_Ps[(size_t)sSrc[rA] * 128 + c0]);
        float4 pB = *reinterpret_cast<const float4*>(&g_Pd[(size_t)sDst[rA + 1] * 128 + c0]);
        float4 qB = *reinterpret_cast<const float4*>(&g_Ps[(size_t)sSrc[rA + 1] * 128 + c0]);
        acc[p][0] = pk2(pA.x + qA.x, pB.x + qB.x);
        acc[p][1] = pk2(pA.y + qA.y, pB.y + qB.y);
        acc[p][2] = pk2(pA.z + qA.z, pB.z + qB.z);
        acc[p][3] = pk2(pA.w + qA.w, pB.w + qB.w);
    }
    gemmA(acc, W0, 128, 64, sInT, c0, r0);
    relu_store_hT(acc, sHT, c0, r0);
    __syncthreads();

    // layer 2: 128 -> 64, config B, residual + store + aggregate
    int c0b = 16 * w + (l & 3) * 4, r0b = (l >> 2) * 4;
    ull acc2[2][4];
    init_bias<2>(acc2, b1, c0b);
    gemmB(acc2, W1, 64, 128, sHT, c0b, r0b);

#pragma unroll
    for (int p = 0; p < 2; p++) {
        int rA = r0b + 2 * p;
        int eA = base + rA;
        int dA = sDst[rA], dB = sDst[rA + 1];
#pragma unroll
        for (int c = 0; c < 4; c++) {
            int col = c0b + c;
            ull oldp = *reinterpret_cast<const ull*>(&sInT[col * SROW + rA]);
            ull np = add2(oldp, acc2[p][c]);
            float a, b;
            upk2(np, a, b);
            if (eA < E) {
                g_edge_tail[(size_t)eA * 64 + col] = a;
                atomicAdd(&g_agg[(size_t)dA * 64 + col], a);
            }
            if (eA + 1 < E) {
                g_edge_tail[(size_t)(eA + 1) * 64 + col] = b;
                atomicAdd(&g_agg[(size_t)dB * 64 + col], b);
            }
        }
    }
}

// ---------------------------------------------------------------------------
// core node step: ninp = [agg/count, node_tail] (K=128) -> 128 relu -> 64
//                 node_tail += out
// ---------------------------------------------------------------------------
__global__ void __launch_bounds__(128)
k_node_core(const float* __restrict__ W0, const float* __restrict__ b0,
            const float* __restrict__ W1, const float* __restrict__ b1, int N) {
    __shared__ float sInT[128 * SROW];
    __shared__ float sHT[128 * SROW];
    __shared__ float sInv[32];
    int t = threadIdx.x;
    int base = blockIdx.x * 32;

    if (t < 32) {
        int n = min(base + t, N - 1);
        sInv[t] = 1.0f / fmaxf(g_counts[n], 1.0f);
    }
    __syncthreads();
    for (int i = t; i < 32 * 128; i += 128) {
        int r = i >> 7, k = i & 127;
        int n = min(base + r, N - 1);
        float v = (k < 64) ? g_agg[(size_t)n * 64 + k] * sInv[r]
                           : g_node[(size_t)n * 128 + 64 + (k - 64)];
        sInT[k * SROW + r] = v;
    }
    __syncthreads();

    int w = t >> 5, l = t & 31;
    int c0 = 32 * w + (l & 7) * 4, r0 = (l >> 3) * 8;
    ull acc[4][4];
    init_bias<4>(acc, b0, c0);
    gemmA(acc, W0, 128, 128, sInT, c0, r0);
    relu_store_hT(acc, sHT, c0, r0);
    __syncthreads();

    int c0b = 16 * w + (l & 3) * 4, r0b = (l >> 2) * 4;
    ull acc2[2][4];
    init_bias<2>(acc2, b1, c0b);
    gemmB(acc2, W1, 64, 128, sHT, c0b, r0b);

#pragma unroll
    for (int p = 0; p < 2; p++) {
        int rA = r0b + 2 * p;
        int nA = base + rA;
#pragma unroll
        for (int c = 0; c < 4; c++) {
            int col = c0b + c;
            ull oldp = *reinterpret_cast<const ull*>(&sInT[(64 + col) * SROW + rA]);
            ull np = add2(oldp, acc2[p][c]);
            float a, b;
            upk2(np, a, b);
            if (nA < N)     g_node[(size_t)nA * 128 + 64 + col] = a;
            if (nA + 1 < N) g_node[(size_t)(nA + 1) * 128 + 64 + col] = b;
        }
    }
}

// ---------------------------------------------------------------------------
// decode: node (K=128) -> 128 relu -> 3
// ---------------------------------------------------------------------------
__global__ void __launch_bounds__(128)
k_decode(const float* __restrict__ W0, const float* __restrict__ b0,
         const float* __restrict__ W1, const float* __restrict__ b1,
         float* __restrict__ out, int N) {
    __shared__ float sInT[128 * SROW];
    __shared__ float sHT[128 * SROW];
    int t = threadIdx.x;
    int base = blockIdx.x * 32;

    for (int i = t; i < 32 * 128; i += 128) {
        int r = i >> 7, k = i & 127;
        int n = min(base + r, N - 1);
        sInT[k * SROW + r] = g_node[(size_t)n * 128 + k];
    }
    __syncthreads();

    int w = t >> 5, l = t & 31;
    int c0 = 32 * w + (l & 7) * 4, r0 = (l >> 3) * 8;
    ull acc[4][4];
    init_bias<4>(acc, b0, c0);
    gemmA(acc, W0, 128, 128, sInT, c0, r0);
    relu_store_hT(acc, sHT, c0, r0);
    __syncthreads();

    if (t < 96) {
        int r = t / 3, c = t - 3 * (t / 3);
        float s = b1[c];
#pragma unroll 8
        for (int j = 0; j < 128; j++) s += sHT[j * SROW + r] * W1[j * 3 + c];
        int n = base + r;
        if (n < N) out[n * 3 + c] = s;
    }
}

// ---------------------------------------------------------------------------
// launch
// ---------------------------------------------------------------------------
extern "C" void kernel_launch(void* const* d_in, const int* in_sizes, int n_in,
                              void* d_out, int out_size) {
    (void)n_in; (void)out_size;
    const int*   ei   = (const int*)d_in[0];
    const float* nf   = (const float*)d_in[1];
    const float* ef   = (const float*)d_in[2];
    const float* emb  = (const float*)d_in[3];
    const float* enW0 = (const float*)d_in[4],  *enb0 = (const float*)d_in[5];
    const float* enW1 = (const float*)d_in[6],  *enb1 = (const float*)d_in[7];
    const float* eeW0 = (const float*)d_in[8],  *eeb0 = (const float*)d_in[9];
    const float* eeW1 = (const float*)d_in[10], *eeb1 = (const float*)d_in[11];
    const float* ceW0 = (const float*)d_in[12], *ceb0 = (const float*)d_in[13];
    const float* ceW1 = (const float*)d_in[14], *ceb1 = (const float*)d_in[15];
    const float* cnW0 = (const float*)d_in[16], *cnb0 = (const float*)d_in[17];
    const float* cnW1 = (const float*)d_in[18], *cnb1 = (const float*)d_in[19];
    const float* dW0  = (const float*)d_in[20], *db0  = (const float*)d_in[21];
    const float* dW1  = (const float*)d_in[22], *db1  = (const float*)d_in[23];
    float* out = (float*)d_out;

    int N = in_sizes[1] / 32;
    int E = in_sizes[0] / 2;
    int nb = (N + 31) / 32;
    int eb = (E + 31) / 32;

    k_zero_counts<<<(N + 255) / 256, 256>>>(N);
    k_counts<<<(E + 255) / 256, 256>>>(ei, E);
    k_encode_node<<<nb, 128>>>(nf, emb, enW0, enb0, enW1, enb1, N);
    k_encode_edge<<<eb, 128>>>(ef, eeW0, eeb0, eeW1, eeb1, E);

    for (int s = 0; s < 3; s++) {
        k_zero_agg<<<(N * 64 + 255) / 256, 256>>>(N * 64);
        k_node_proj<<<nb, 128>>>(ceW0, ceb0, N);
        k_edge_core<<<eb, 128>>>(ei, ceW0, ceW1, ceb1, E);
        k_node_core<<<nb, 128>>>(cnW0, cnb0, cnW1, cnb1, N);
    }

    k_decode<<<nb, 128>>>(dW0, db0, dW1, db1, out, N);
}

// round 11
// speedup vs baseline: 1.3078x; 1.3078x over previous
#include <cuda_runtime.h>
#include <cstdint>

#define SROW 36
#define MAXN 50048
#define MAXE 800032
typedef unsigned long long ull;

__device__ float g_node[(size_t)MAXN * 128];
__device__ float g_edge_tail[(size_t)MAXE * 64];
__device__ float g_agg[(size_t)MAXN * 64];
__device__ float g_counts[MAXN];
__device__ float g_W0T[128 * 192];   // core_e_W0^T [n=128][k=192], tf32-rounded
__device__ float g_W1T[64 * 128];    // core_e_W1^T [n=64][k=128]
__device__ float g_eW0T[128 * 8];    // enc_e_W0^T  [n=128][k=8 pad, k>=3 zero]
__device__ float g_eW1T[64 * 128];   // enc_e_W1[:,64:]^T

// ---------------- tf32 mma.sync helpers ----------------
__device__ __forceinline__ uint32_t f2tf(float x) {
    uint32_t u; asm("cvt.rna.tf32.f32 %0, %1;" : "=r"(u) : "f"(x));
    return u;
}
#define MMA8(d, a0, a1, a2, a3, b0, b1)                                        \
    asm volatile(                                                              \
        "mma.sync.aligned.m16n8k8.row.col.f32.tf32.tf32.f32 "                  \
        "{%0,%1,%2,%3}, {%4,%5,%6,%7}, {%8,%9}, {%0,%1,%2,%3};"                \
        : "+f"((d)[0]), "+f"((d)[1]), "+f"((d)[2]), "+f"((d)[3])               \
        : "r"(a0), "r"(a1), "r"(a2), "r"(a3), "r"(b0), "r"(b1))

// ---------------- small kernels ----------------
__global__ void k_prep(const float* __restrict__ ceW0, const float* __restrict__ ceW1,
                       const float* __restrict__ eeW0, const float* __restrict__ eeW1) {
    int i = blockIdx.x * 256 + threadIdx.x;
    if (i < 128 * 192) { int n = i / 192, k = i % 192; g_W0T[i] = __uint_as_float(f2tf(ceW0[k * 128 + n])); }
    int j = i - 128 * 192;
    if (j >= 0 && j < 64 * 128) { int n = j / 128, k = j % 128; g_W1T[j] = __uint_as_float(f2tf(ceW1[k * 64 + n])); }
    int m = j - 64 * 128;
    if (m >= 0 && m < 128 * 8) { int n = m / 8, k = m % 8; g_eW0T[m] = (k < 3) ? __uint_as_float(f2tf(eeW0[k * 128 + n])) : 0.f; }
    int q = m - 128 * 8;
    if (q >= 0 && q < 64 * 128) { int n = q / 128, k = q % 128; g_eW1T[q] = __uint_as_float(f2tf(eeW1[k * 128 + 64 + n])); }
}
__global__ void k_zero_counts(int n) { int i = blockIdx.x*256+threadIdx.x; if (i < n) g_counts[i] = 0.f; }
__global__ void k_zero_agg(int n)    { int i = blockIdx.x*256+threadIdx.x; if (i < n) g_agg[i] = 0.f; }
__global__ void k_counts(const int* __restrict__ ei, int E) {
    int e = blockIdx.x*256+threadIdx.x;
    if (e < E) atomicAdd(&g_counts[ei[E + e]], 1.0f);
}

// ---------------------------------------------------------------------------
// core edge step, tensor (tf32 mma.sync):
//   D1 = [tail|dst_tail|src_tail] @ W0 ; h = relu(D1+b0)
//   D2 = h @ W1 ; tail += D2 + b1 ; store ; atomicAdd agg[dst]
// smem: sW0[128][196] | sW1[64][132] | sA[128][68] | idx[256]
// ---------------------------------------------------------------------------
#define T_CORE 4
#define W1_OFF 25088
#define A_OFF  33536
#define IDX_OFF 42240
__global__ void __launch_bounds__(256, 1)
k_edge_core_mma(const int* __restrict__ ei, const float* __restrict__ b0g,
                const float* __restrict__ b1g, int E) {
    extern __shared__ float sm[];
    float* sW0 = sm;
    float* sW1 = sm + W1_OFF;
    float* sA  = sm + A_OFF;
    int*   sIdx = (int*)(sm + IDX_OFF);   // [0:128) dst, [128:256) src
    int t = threadIdx.x, w = t >> 5, lane = t & 31;
    int tg = lane & 3, lg = lane >> 2, rb = 16 * w;

    for (int i = t; i < 128 * 48; i += 256) {
        int n = i / 48, j = i % 48;
        *(float4*)(sW0 + n * 196 + j * 4) = *(const float4*)(g_W0T + n * 192 + j * 4);
    }
    for (int i = t; i < 64 * 32; i += 256) {
        int n = i / 32, j = i % 32;
        *(float4*)(sW1 + n * 132 + j * 4) = *(const float4*)(g_W1T + n * 128 + j * 4);
    }
    __syncthreads();

    for (int tt = 0; tt < T_CORE; tt++) {
        int base = (blockIdx.x * T_CORE + tt) * 128;
        if (base >= E) break;
        __syncthreads();                          // prior tile done with sIdx
        if (t < 128) {
            int e = min(base + t, E - 1);
            sIdx[t] = ei[E + e];
            sIdx[128 + t] = ei[e];
        }
        __syncthreads();

        float d1[16][4];
#pragma unroll
        for (int n0 = 0; n0 < 16; n0++)
#pragma unroll
            for (int c = 0; c < 4; c++) d1[n0][c] = 0.f;

        int row = t >> 1, half = t & 1;
        int er = min(base + row, E - 1);

        for (int ch = 0; ch < 3; ch++) {
            // gather chunk into warp-private band of sA (tf32-converted)
            const float* p;
            if (ch == 0)      p = g_edge_tail + (size_t)er * 64;
            else if (ch == 1) p = g_node + (size_t)sIdx[row] * 128 + 64;
            else              p = g_node + (size_t)sIdx[128 + row] * 128 + 64;
            p += half * 32;
            float* dst = sA + row * 68 + half * 32;
#pragma unroll
            for (int j = 0; j < 8; j++) {
                float4 v = *(const float4*)(p + j * 4);
                *(float4*)(dst + j * 4) = make_float4(
                    __uint_as_float(f2tf(v.x)), __uint_as_float(f2tf(v.y)),
                    __uint_as_float(f2tf(v.z)), __uint_as_float(f2tf(v.w)));
            }
            __syncwarp();
            // mma over this 64-k chunk
            for (int k0 = 0; k0 < 8; k0++) {
                int kb = k0 * 8 + tg;
                uint32_t a0 = __float_as_uint(sA[(rb + lg) * 68 + kb]);
                uint32_t a1 = __float_as_uint(sA[(rb + lg + 8) * 68 + kb]);
                uint32_t a2 = __float_as_uint(sA[(rb + lg) * 68 + kb + 4]);
                uint32_t a3 = __float_as_uint(sA[(rb + lg + 8) * 68 + kb + 4]);
                int kg = ch * 64 + k0 * 8 + tg;
#pragma unroll
                for (int n0 = 0; n0 < 16; n0++) {
                    uint32_t b0 = __float_as_uint(sW0[(n0 * 8 + lg) * 196 + kg]);
                    uint32_t b1 = __float_as_uint(sW0[(n0 * 8 + lg) * 196 + kg + 4]);
                    MMA8(d1[n0], a0, a1, a2, a3, b0, b1);
                }
            }
            __syncwarp();
        }

        // epilogue1 halves + layer2
        float d2[8][4];
#pragma unroll
        for (int n0 = 0; n0 < 8; n0++)
#pragma unroll
            for (int c = 0; c < 4; c++) d2[n0][c] = 0.f;

        for (int nh = 0; nh < 2; nh++) {
#pragma unroll
            for (int q = 0; q < 8; q++) {
                int n0 = nh * 8 + q;
                int c0 = n0 * 8 + 2 * tg, cl = c0 - nh * 64;
                float ba = __ldg(b0g + c0), bb = __ldg(b0g + c0 + 1);
                float h0 = fmaxf(d1[n0][0] + ba, 0.f), h1 = fmaxf(d1[n0][1] + bb, 0.f);
                float h2 = fmaxf(d1[n0][2] + ba, 0.f), h3 = fmaxf(d1[n0][3] + bb, 0.f);
                *(float2*)(sA + (rb + lg) * 68 + cl) =
                    make_float2(__uint_as_float(f2tf(h0)), __uint_as_float(f2tf(h1)));
                *(float2*)(sA + (rb + lg + 8) * 68 + cl) =
                    make_float2(__uint_as_float(f2tf(h2)), __uint_as_float(f2tf(h3)));
            }
            __syncwarp();
            for (int k0 = 0; k0 < 8; k0++) {
                int kb = k0 * 8 + tg;
                uint32_t a0 = __float_as_uint(sA[(rb + lg) * 68 + kb]);
                uint32_t a1 = __float_as_uint(sA[(rb + lg + 8) * 68 + kb]);
                uint32_t a2 = __float_as_uint(sA[(rb + lg) * 68 + kb + 4]);
                uint32_t a3 = __float_as_uint(sA[(rb + lg + 8) * 68 + kb + 4]);
                int kg = nh * 64 + k0 * 8 + tg;
#pragma unroll
                for (int n0 = 0; n0 < 8; n0++) {
                    uint32_t b0 = __float_as_uint(sW1[(n0 * 8 + lg) * 132 + kg]);
                    uint32_t b1 = __float_as_uint(sW1[(n0 * 8 + lg) * 132 + kg + 4]);
                    MMA8(d2[n0], a0, a1, a2, a3, b0, b1);
                }
            }
            __syncwarp();
        }

        // epilogue2: residual + bias, store tail, aggregate
        int r0 = rb + lg, r1 = r0 + 8;
#pragma unroll
        for (int n0 = 0; n0 < 8; n0++) {
            int c = n0 * 8 + 2 * tg;
            float ba = __ldg(b1g + c), bb = __ldg(b1g + c + 1);
            int e0 = base + r0;
            if (e0 < E) {
                float2 rv = *(const float2*)(g_edge_tail + (size_t)e0 * 64 + c);
                float x0 = d2[n0][0] + ba + rv.x, x1 = d2[n0][1] + bb + rv.y;
                *(float2*)(g_edge_tail + (size_t)e0 * 64 + c) = make_float2(x0, x1);
                float* pa = g_agg + (size_t)sIdx[r0] * 64 + c;
                atomicAdd(pa, x0); atomicAdd(pa + 1, x1);
            }
            int e1 = base + r1;
            if (e1 < E) {
                float2 rv = *(const float2*)(g_edge_tail + (size_t)e1 * 64 + c);
                float x0 = d2[n0][2] + ba + rv.x, x1 = d2[n0][3] + bb + rv.y;
                *(float2*)(g_edge_tail + (size_t)e1 * 64 + c) = make_float2(x0, x1);
                float* pa = g_agg + (size_t)sIdx[r1] * 64 + c;
                atomicAdd(pa, x0); atomicAdd(pa + 1, x1);
            }
        }
    }
}

// ---------------------------------------------------------------------------
// encode edge, tensor: ef (K=3 pad 8) -> 128 relu -> cols 64..127 -> g_edge_tail
// smem: sW0[128][12] | sW1[64][132] | sA[128][68]
// ---------------------------------------------------------------------------
#define T_ENC 8
#define EW1_OFF 1536
#define EA_OFF  9984
__global__ void __launch_bounds__(256, 1)
k_encode_edge_mma(const float* __restrict__ ef, const float* __restrict__ b0g,
                  const float* __restrict__ b1g, int E) {
    extern __shared__ float sm[];
    float* sW0 = sm;
    float* sW1 = sm + EW1_OFF;
    float* sA  = sm + EA_OFF;
    int t = threadIdx.x, w = t >> 5, lane = t & 31;
    int tg = lane & 3, lg = lane >> 2, rb = 16 * w;

    for (int i = t; i < 128 * 2; i += 256) {
        int n = i / 2, j = i % 2;
        *(float4*)(sW0 + n * 12 + j * 4) = *(const float4*)(g_eW0T + n * 8 + j * 4);
    }
    for (int i = t; i < 64 * 32; i += 256) {
        int n = i / 32, j = i % 32;
        *(float4*)(sW1 + n * 132 + j * 4) = *(const float4*)(g_eW1T + n * 128 + j * 4);
    }
    __syncthreads();

    for (int tt = 0; tt < T_ENC; tt++) {
        int base = (blockIdx.x * T_ENC + tt) * 128;
        if (base >= E) break;
        int row = t >> 1, half = t & 1;
        int er = min(base + row, E - 1);
        {   // gather: half0 -> k 0..3 (ef + pad), half1 -> k 4..7 zeros
            float* dst = sA + row * 68 + half * 4;
            if (half == 0) {
                *(float4*)dst = make_float4(
                    __uint_as_float(f2tf(ef[er * 3 + 0])),
                    __uint_as_float(f2tf(ef[er * 3 + 1])),
                    __uint_as_float(f2tf(ef[er * 3 + 2])), 0.f);
            } else {
                *(float4*)dst = make_float4(0.f, 0.f, 0.f, 0.f);
            }
        }
        __syncwarp();

        float d1[16][4];
#pragma unroll
        for (int n0 = 0; n0 < 16; n0++)
#pragma unroll
            for (int c = 0; c < 4; c++) d1[n0][c] = 0.f;
        {   // single k-step
            uint32_t a0 = __float_as_uint(sA[(rb + lg) * 68 + tg]);
            uint32_t a1 = __float_as_uint(sA[(rb + lg + 8) * 68 + tg]);
            uint32_t a2 = __float_as_uint(sA[(rb + lg) * 68 + tg + 4]);
            uint32_t a3 = __float_as_uint(sA[(rb + lg + 8) * 68 + tg + 4]);
#pragma unroll
            for (int n0 = 0; n0 < 16; n0++) {
                uint32_t b0 = __float_as_uint(sW0[(n0 * 8 + lg) * 12 + tg]);
                uint32_t b1 = __float_as_uint(sW0[(n0 * 8 + lg) * 12 + tg + 4]);
                MMA8(d1[n0], a0, a1, a2, a3, b0, b1);
            }
        }
        __syncwarp();

        float d2[8][4];
#pragma unroll
        for (int n0 = 0; n0 < 8; n0++)
#pragma unroll
            for (int c = 0; c < 4; c++) d2[n0][c] = 0.f;

        for (int nh = 0; nh < 2; nh++) {
#pragma unroll
            for (int q = 0; q < 8; q++) {
                int n0 = nh * 8 + q;
                int c0 = n0 * 8 + 2 * tg, cl = c0 - nh * 64;
                float ba = __ldg(b0g + c0), bb = __ldg(b0g + c0 + 1);
                float h0 = fmaxf(d1[n0][0] + ba, 0.f), h1 = fmaxf(d1[n0][1] + bb, 0.f);
                float h2 = fmaxf(d1[n0][2] + ba, 0.f), h3 = fmaxf(d1[n0][3] + bb, 0.f);
                *(float2*)(sA + (rb + lg) * 68 + cl) =
                    make_float2(__uint_as_float(f2tf(h0)), __uint_as_float(f2tf(h1)));
                *(float2*)(sA + (rb + lg + 8) * 68 + cl) =
                    make_float2(__uint_as_float(f2tf(h2)), __uint_as_float(f2tf(h3)));
            }
            __syncwarp();
            for (int k0 = 0; k0 < 8; k0++) {
                int kb = k0 * 8 + tg;
                uint32_t a0 = __float_as_uint(sA[(rb + lg) * 68 + kb]);
                uint32_t a1 = __float_as_uint(sA[(rb + lg + 8) * 68 + kb]);
                uint32_t a2 = __float_as_uint(sA[(rb + lg) * 68 + kb + 4]);
                uint32_t a3 = __float_as_uint(sA[(rb + lg + 8) * 68 + kb + 4]);
                int kg = nh * 64 + k0 * 8 + tg;
#pragma unroll
                for (int n0 = 0; n0 < 8; n0++) {
                    uint32_t b0 = __float_as_uint(sW1[(n0 * 8 + lg) * 132 + kg]);
                    uint32_t b1 = __float_as_uint(sW1[(n0 * 8 + lg) * 132 + kg + 4]);
                    MMA8(d2[n0], a0, a1, a2, a3, b0, b1);
                }
            }
            __syncwarp();
        }

        int r0 = rb + lg, r1 = r0 + 8;
#pragma unroll
        for (int n0 = 0; n0 < 8; n0++) {
            int c = n0 * 8 + 2 * tg;
            float ba = __ldg(b1g + c), bb = __ldg(b1g + c + 1);
            int e0 = base + r0;
            if (e0 < E)
                *(float2*)(g_edge_tail + (size_t)e0 * 64 + c) =
                    make_float2(d2[n0][0] + ba, d2[n0][1] + bb);
            int e1 = base + r1;
            if (e1 < E)
                *(float2*)(g_edge_tail + (size_t)e1 * 64 + c) =
                    make_float2(d2[n0][2] + ba, d2[n0][3] + bb);
        }
        __syncwarp();
    }
}

// ---------------- scalar fp32 node-side (passing round-6 design) ----------------
__device__ __forceinline__ ull pk2(float a, float b) { ull r; asm("mov.b64 %0, {%1, %2};" : "=l"(r) : "f"(a), "f"(b)); return r; }
__device__ __forceinline__ void upk2(ull v, float &a, float &b) { asm("mov.b64 {%0, %1}, %2;" : "=f"(a), "=f"(b) : "l"(v)); }
__device__ __forceinline__ void fma2(ull &d, ull a, ull b) { asm("fma.rn.f32x2 %0, %1, %2, %3;" : "=l"(d) : "l"(a), "l"(b), "l"(d)); }
__device__ __forceinline__ ull add2(ull a, ull b) { ull r; asm("add.rn.f32x2 %0, %1, %2;" : "=l"(r) : "l"(a), "l"(b)); return r; }
__device__ __forceinline__ void gemmA(ull (&acc)[4][4], const float* __restrict__ W, int ld, int K,
                                      const float* sInT, int c0, int r0) {
#pragma unroll 4
    for (int k = 0; k < K; k++) {
        float4 w = __ldg(reinterpret_cast<const float4*>(W + (size_t)k * ld + c0));
        ull w0 = pk2(w.x, w.x), w1 = pk2(w.y, w.y), w2 = pk2(w.z, w.z), w3 = pk2(w.w, w.w);
        const float* row = sInT + k * SROW + r0;
        ulonglong2 xa = *reinterpret_cast<const ulonglong2*>(row);
        ulonglong2 xb = *reinterpret_cast<const ulonglong2*>(row + 4);
        fma2(acc[0][0], xa.x, w0); fma2(acc[0][1], xa.x, w1); fma2(acc[0][2], xa.x, w2); fma2(acc[0][3], xa.x, w3);
        fma2(acc[1][0], xa.y, w0); fma2(acc[1][1], xa.y, w1); fma2(acc[1][2], xa.y, w2); fma2(acc[1][3], xa.y, w3);
        fma2(acc[2][0], xb.x, w0); fma2(acc[2][1], xb.x, w1); fma2(acc[2][2], xb.x, w2); fma2(acc[2][3], xb.x, w3);
        fma2(acc[3][0], xb.y, w0); fma2(acc[3][1], xb.y, w1); fma2(acc[3][2], xb.y, w2); fma2(acc[3][3], xb.y, w3);
    }
}
__device__ __forceinline__ void gemmB(ull (&acc)[2][4], const float* __restrict__ W, int ld, int K,
                                      const float* sInT, int c0, int r0) {
#pragma unroll 4
    for (int k = 0; k < K; k++) {
        float4 w = __ldg(reinterpret_cast<const float4*>(W + (size_t)k * ld + c0));
        ull w0 = pk2(w.x, w.x), w1 = pk2(w.y, w.y), w2 = pk2(w.z, w.z), w3 = pk2(w.w, w.w);
        ulonglong2 xa = *reinterpret_cast<const ulonglong2*>(sInT + k * SROW + r0);
        fma2(acc[0][0], xa.x, w0); fma2(acc[0][1], xa.x, w1); fma2(acc[0][2], xa.x, w2); fma2(acc[0][3], xa.x, w3);
        fma2(acc[1][0], xa.y, w0); fma2(acc[1][1], xa.y, w1); fma2(acc[1][2], xa.y, w2); fma2(acc[1][3], xa.y, w3);
    }
}
template <int NP>
__device__ __forceinline__ void init_bias(ull (&acc)[NP][4], const float* __restrict__ b, int c0) {
#pragma unroll
    for (int c = 0; c < 4; c++) {
        float bv = b[c0 + c]; ull bb = pk2(bv, bv);
#pragma unroll
        for (int p = 0; p < NP; p++) acc[p][c] = bb;
    }
}
__device__ __forceinline__ void relu_store_hT(ull (&acc)[4][4], float* sHT, int c0, int r0) {
#pragma unroll
    for (int p = 0; p < 4; p++)
#pragma unroll
        for (int c = 0; c < 4; c++) {
            float a, b; upk2(acc[p][c], a, b);
            *reinterpret_cast<float2*>(&sHT[(c0 + c) * SROW + r0 + 2 * p]) =
                make_float2(fmaxf(a, 0.f), fmaxf(b, 0.f));
        }
}

__global__ void __launch_bounds__(128)
k_encode_node(const float* __restrict__ nf, const float* __restrict__ emb,
              const float* __restrict__ W0, const float* __restrict__ b0,
              const float* __restrict__ W1, const float* __restrict__ b1, int N) {
    __shared__ float sInT[47 * SROW];
    __shared__ float sHT[128 * SROW];
    __shared__ int sPT[32];
    int t = threadIdx.x, base = blockIdx.x * 32;
    if (t < 32) { int n = min(base + t, N - 1); sPT[t] = (int)(nf[n * 32 + 31] + 0.5f); }
    __syncthreads();
    for (int i = t; i < 32 * 47; i += 128) {
        int r = i / 47, k = i - r * 47;
        int n = min(base + r, N - 1);
        sInT[k * SROW + r] = (k < 31) ? nf[n * 32 + k] : emb[sPT[r] * 16 + (k - 31)];
    }
    __syncthreads();
    int w = t >> 5, l = t & 31;
    int c0 = 32 * w + (l & 7) * 4, r0 = (l >> 3) * 8;
    ull acc[4][4];
    init_bias<4>(acc, b0, c0);
    gemmA(acc, W0, 128, 47, sInT, c0, r0);
    relu_store_hT(acc, sHT, c0, r0);
    __syncthreads();
    ull acc2[4][4];
    init_bias<4>(acc2, b1, c0);
    gemmA(acc2, W1, 128, 128, sHT, c0, r0);
#pragma unroll
    for (int p = 0; p < 4; p++)
#pragma unroll
        for (int c = 0; c < 4; c++) {
            float a, b; upk2(acc2[p][c], a, b);
            int rA = base + r0 + 2 * p;
            if (rA < N)     g_node[(size_t)rA * 128 + c0 + c] = a;
            if (rA + 1 < N) g_node[(size_t)(rA + 1) * 128 + c0 + c] = b;
        }
}

__global__ void __launch_bounds__(128)
k_node_core(const float* __restrict__ W0, const float* __restrict__ b0,
            const float* __restrict__ W1, const float* __restrict__ b1, int N) {
    __shared__ float sInT[128 * SROW];
    __shared__ float sHT[128 * SROW];
    __shared__ float sInv[32];
    int t = threadIdx.x, base = blockIdx.x * 32;
    if (t < 32) { int n = min(base + t, N - 1); sInv[t] = 1.0f / fmaxf(g_counts[n], 1.0f); }
    __syncthreads();
    for (int i = t; i < 32 * 128; i += 128) {
        int r = i >> 7, k = i & 127;
        int n = min(base + r, N - 1);
        sInT[k * SROW + r] = (k < 64) ? g_agg[(size_t)n * 64 + k] * sInv[r]
                                      : g_node[(size_t)n * 128 + 64 + (k - 64)];
    }
    __syncthreads();
    int w = t >> 5, l = t & 31;
    int c0 = 32 * w + (l & 7) * 4, r0 = (l >> 3) * 8;
    ull acc[4][4];
    init_bias<4>(acc, b0, c0);
    gemmA(acc, W0, 128, 128, sInT, c0, r0);
    relu_store_hT(acc, sHT, c0, r0);
    __syncthreads();
    int c0b = 16 * w + (l & 3) * 4, r0b = (l >> 2) * 4;
    ull acc2[2][4];
    init_bias<2>(acc2, b1, c0b);
    gemmB(acc2, W1, 64, 128, sHT, c0b, r0b);
#pragma unroll
    for (int p = 0; p < 2; p++) {
        int rA = r0b + 2 * p, nA = base + rA;
#pragma unroll
        for (int c = 0; c < 4; c++) {
            int col = c0b + c;
            ull oldp = *reinterpret_cast<const ull*>(&sInT[(64 + col) * SROW + rA]);
            ull np = add2(oldp, acc2[p][c]);
            float a, b; upk2(np, a, b);
            if (nA < N)     g_node[(size_t)nA * 128 + 64 + col] = a;
            if (nA + 1 < N) g_node[(size_t)(nA + 1) * 128 + 64 + col] = b;
        }
    }
}

__global__ void __launch_bounds__(128)
k_decode(const float* __restrict__ W0, const float* __restrict__ b0,
         const float* __restrict__ W1, const float* __restrict__ b1,
         float* __restrict__ out, int N) {
    __shared__ float sInT[128 * SROW];
    __shared__ float sHT[128 * SROW];
    int t = threadIdx.x, base = blockIdx.x * 32;
    for (int i = t; i < 32 * 128; i += 128) {
        int r = i >> 7, k = i & 127;
        int n = min(base + r, N - 1);
        sInT[k * SROW + r] = g_node[(size_t)n * 128 + k];
    }
    __syncthreads();
    int w = t >> 5, l = t & 31;
    int c0 = 32 * w + (l & 7) * 4, r0 = (l >> 3) * 8;
    ull acc[4][4];
    init_bias<4>(acc, b0, c0);
    gemmA(acc, W0, 128, 128, sInT, c0, r0);
    relu_store_hT(acc, sHT, c0, r0);
    __syncthreads();
    if (t < 96) {
        int r = t / 3, c = t - 3 * (t / 3);
        float s = b1[c];
#pragma unroll 8
        for (int j = 0; j < 128; j++) s += sHT[j * SROW + r] * W1[j * 3 + c];
        int n = base + r;
        if (n < N) out[n * 3 + c] = s;
    }
}

// ---------------- launch ----------------
extern "C" void kernel_launch(void* const* d_in, const int* in_sizes, int n_in,
                              void* d_out, int out_size) {
    (void)n_in; (void)out_size;
    const int*   ei   = (const int*)d_in[0];
    const float* nf   = (const float*)d_in[1];
    const float* ef   = (const float*)d_in[2];
    const float* emb  = (const float*)d_in[3];
    const float* enW0 = (const float*)d_in[4],  *enb0 = (const float*)d_in[5];
    const float* enW1 = (const float*)d_in[6],  *enb1 = (const float*)d_in[7];
    const float* eeW0 = (const float*)d_in[8],  *eeb0 = (const float*)d_in[9];
    const float* eeW1 = (const float*)d_in[10], *eeb1 = (const float*)d_in[11];
    const float* ceW0 = (const float*)d_in[12], *ceb0 = (const float*)d_in[13];
    const float* ceW1 = (const float*)d_in[14], *ceb1 = (const float*)d_in[15];
    const float* cnW0 = (const float*)d_in[16], *cnb0 = (const float*)d_in[17];
    const float* cnW1 = (const float*)d_in[18], *cnb1 = (const float*)d_in[19];
    const float* dW0  = (const float*)d_in[20], *db0  = (const float*)d_in[21];
    const float* dW1  = (const float*)d_in[22], *db1  = (const float*)d_in[23];
    float* out = (float*)d_out;

    int N = in_sizes[1] / 32;
    int E = in_sizes[0] / 2;
    int nb = (N + 31) / 32;

    const int SM_CORE = IDX_OFF * 4 + 256 * 4;          // 170,  (42240*4 + 1024)
    const int SM_ENC  = (EA_OFF + 128 * 68) * 4;        // 74752
    cudaFuncSetAttribute(k_edge_core_mma, cudaFuncAttributeMaxDynamicSharedMemorySize, SM_CORE);
    cudaFuncSetAttribute(k_encode_edge_mma, cudaFuncAttributeMaxDynamicSharedMemorySize, SM_ENC);

    int prep_tot = 128 * 192 + 64 * 128 + 128 * 8 + 64 * 128;
    k_prep<<<(prep_tot + 255) / 256, 256>>>(ceW0, ceW1, eeW0, eeW1);
    k_zero_counts<<<(N + 255) / 256, 256>>>(N);
    k_counts<<<(E + 255) / 256, 256>>>(ei, E);
    k_encode_node<<<nb, 128>>>(nf, emb, enW0, enb0, enW1, enb1, N);

    int enc_b = (E + 128 * T_ENC - 1) / (128 * T_ENC);
    k_encode_edge_mma<<<enc_b, 256, SM_ENC>>>(ef, eeb0, eeb1 + 64, E);

    int core_b = (E + 128 * T_CORE - 1) / (128 * T_CORE);
    for (int s = 0; s < 3; s++) {
        k_zero_agg<<<(N * 64 + 255) / 256, 256>>>(N * 64);
        k_edge_core_mma<<<core_b, 256, SM_CORE>>>(ei, ceb0, ceb1, E);
        k_node_core<<<nb, 128>>>(cnW0, cnb0, cnW1, cnb1, N);
    }
    k_decode<<<nb, 128>>>(dW0, db0, dW1, db1, out, N);
}